// round 9
// baseline (speedup 1.0000x reference)
#include <cuda_runtime.h>
#include <cstdint>

#define BB 32
#define TT 36
#define NN 10000
#define FF 3
#define HH 10
#define RR 20

#define THREADS 256
#define TILE    1024            // nodes per CTA
#define GXB     10              // ceil(NN / TILE)
#define NCTA    (GXB * BB)      // 320
#define STAGES  8
#define ROWB    (TILE * FF * 4) // 12288 bytes per (row, tile)
#define ROWF    (TILE * FF)     // 3072 floats
#define SMEMB   (STAGES * ROWB) // 98304
#define NANCAP  4096

// ---- device scratch (zero-initialized at load; finalizer re-zeros) ----
__device__ float    g_rsum[BB * RR];
__device__ float    g_rcnt[BB * RR];
__device__ unsigned g_done = 0;
__device__ int      g_nan_n = 0;
__device__ int      g_nan_list[NANCAP];

__device__ __forceinline__ void cp_async16(uint32_t dst, const void* src, int src_sz) {
    asm volatile("cp.async.cg.shared.global [%0], [%1], 16, %2;"
                 :: "r"(dst), "l"(src), "r"(src_sz) : "memory");
}
__device__ __forceinline__ void cp_commit() {
    asm volatile("cp.async.commit_group;" ::: "memory");
}
template <int N>
__device__ __forceinline__ void cp_wait() {
    asm volatile("cp.async.wait_group %0;" :: "n"(N) : "memory");
}

extern __shared__ float sm[];

// ---------------------------------------------------------------------------
__global__ void __launch_bounds__(THREADS, 2)
k_main(const float* __restrict__ seq, const int* __restrict__ cid32,
       float* __restrict__ out) {
    const int tid = threadIdx.x;
    const int b   = blockIdx.y;
    const int n0  = blockIdx.x * TILE;
    const int validN = min(TILE, NN - n0);         // 1024 or 784 (last tile)
    const int validB = validN * FF * 4;            // valid bytes per row

    __shared__ float srs[RR], src_[RR];
    __shared__ int   s_is64;
    if (tid < RR) { srs[tid] = 0.f; src_[tid] = 0.f; }
    if (tid < 32) {
        // int64-LE cluster_id => odd int32 words (upper halves) all zero
        unsigned m = __ballot_sync(0xffffffffu, cid32[2 * tid + 1] == 0);
        if (tid == 0) s_is64 = (__popc(m) > 16);
    }
    __syncthreads();

    const uint32_t smb = (uint32_t)__cvta_generic_to_shared(sm);
    const char* grow = (const char*)(seq) + ((size_t)b * TT * NN + n0) * (FF * 4);
    const size_t rowStride = (size_t)NN * FF * 4;  // 120000 B, 16B-aligned

    // issue one row's 3x16B per thread (zfill beyond validB)
    auto issue_row = [&](int t) {
        const char* g = grow + (size_t)t * rowStride;
        const uint32_t d = smb + (uint32_t)(t % STAGES) * ROWB;
#pragma unroll
        for (int p = 0; p < 3; p++) {
            int off = tid * 16 + p * 4096;
            int sz  = validB - off;                 // may be <=0 -> pure zfill
            sz = sz < 0 ? 0 : (sz > 16 ? 16 : sz);
            cp_async16(d + off, g + off, sz);
        }
        cp_commit();
    };

    // ---------------- prologue: fill the ring -----------------------------
#pragma unroll
    for (int t = 0; t < STAGES; t++) issue_row(t);

    float acc_s[4] = {0.f, 0.f, 0.f, 0.f};
    float acc_c[4] = {0.f, 0.f, 0.f, 0.f};

    for (int r = 0; r < TT; r++) {
        if (r < TT - STAGES) cp_wait<STAGES - 1>(); else cp_wait<0>();
        __syncthreads();                            // row r visible to all
        const float* buf = sm + (r % STAGES) * ROWF;
#pragma unroll
        for (int k = 0; k < 4; k++) {
            float v = buf[(tid + k * THREADS) * 3]; // bank = 3*tid%32: conflict-free
            if (v == v) { acc_s[k] += v; acc_c[k] += 1.f; }
        }
        __syncthreads();                            // slot free before reuse
        if (r + STAGES < TT) issue_row(r + STAGES);
    }

    // ---------------- per-node finalize + out_pred + region atomics -------
#pragma unroll
    for (int k = 0; k < 4; k++) {
        const int n = n0 + tid + k * THREADS;
        if (n < NN) {
            const float c  = acc_c[k];
            const float tm = acc_s[k] / c;          // 0/0 -> NaN
            float* op = out + (size_t)b * HH * NN + n;
#pragma unroll
            for (int h = 0; h < HH; h++) __stcs(op + (size_t)h * NN, tm);
            if (c > 0.f) {
                const int rg = s_is64 ? cid32[2 * n] : cid32[n];
                atomicAdd(&srs[rg], tm);
                atomicAdd(&src_[rg], 1.f);
            } else {                                // all-NaN node (p ~ 0)
                int slot = atomicAdd(&g_nan_n, 1);
                if (slot < NANCAP) g_nan_list[slot] = b * NN + n;
            }
        }
    }
    __syncthreads();
    if (tid < RR && src_[tid] != 0.f) {
        atomicAdd(&g_rsum[b * RR + tid], srs[tid]);
        atomicAdd(&g_rcnt[b * RR + tid], src_[tid]);
    }

    // ================= completion: last block finalizes ====================
    __shared__ bool s_last;
    __syncthreads();
    if (tid == 0) {
        __threadfence();
        s_last = (atomicAdd(&g_done, 1u) == NCTA - 1);
    }
    __syncthreads();
    if (!s_last) return;

    __threadfence();

    __shared__ float s_gs, s_gc, s_2s, s_2c;
    if (tid == 0) { s_gs = 0.f; s_gc = 0.f; s_2s = 0.f; s_2c = 0.f; }
    __syncthreads();

    float rs[3], rc[3];                              // 640 pairs / 256 thr
#pragma unroll
    for (int q = 0; q < 3; q++) {
        int pidx = tid + q * THREADS;
        if (pidx < BB * RR) {
            rs[q] = g_rsum[pidx]; rc[q] = g_rcnt[pidx];
            atomicAdd(&s_gs, rs[q]);
            atomicAdd(&s_gc, rc[q]);
            if (rc[q] > 0.f) { atomicAdd(&s_2s, rs[q] / rc[q]); atomicAdd(&s_2c, 1.f); }
        }
    }
    __syncthreads();
    const float g1 = s_gs / s_gc;
    const float g2 = s_2s / s_2c;

    float* oreg = out + (size_t)BB * HH * NN;
#pragma unroll
    for (int q = 0; q < 3; q++) {
        int pidx = tid + q * THREADS;
        if (pidx < BB * RR) {
            float val = (rc[q] > 0.f) ? rs[q] / rc[q] : g2;
            int pb = pidx / RR, pr = pidx % RR;
#pragma unroll
            for (int h = 0; h < HH; h++)
                oreg[(pb * HH + h) * RR + pr] = val;
        }
    }

    int nn = min(g_nan_n, NANCAP);
    for (int i = tid; i < nn; i += THREADS) {
        int idx = g_nan_list[i];
        int nb = idx / NN, nd = idx % NN;
#pragma unroll
        for (int h = 0; h < HH; h++)
            out[((size_t)nb * HH + h) * NN + nd] = g1;
    }

    __syncthreads();
    for (int pidx = tid; pidx < BB * RR; pidx += THREADS) {
        g_rsum[pidx] = 0.f; g_rcnt[pidx] = 0.f;
    }
    if (tid == 0) { g_done = 0; g_nan_n = 0; }
}

// ---------------------------------------------------------------------------
extern "C" void kernel_launch(void* const* d_in, const int* in_sizes, int n_in,
                              void* d_out, int out_size) {
    const float* seq   = (const float*)d_in[0];
    const int*   cid32 = (const int*)d_in[1];
    float*       out   = (float*)d_out;

    cudaFuncSetAttribute(k_main, cudaFuncAttributeMaxDynamicSharedMemorySize, SMEMB);
    dim3 grid(GXB, BB);
    k_main<<<grid, THREADS, SMEMB>>>(seq, cid32, out);
}

// round 10
// speedup vs baseline: 1.2362x; 1.2362x over previous
#include <cuda_runtime.h>
#include <cstdint>

#define BB 32
#define TT 36
#define NN 10000
#define FF 3
#define HH 10
#define RR 20

#define THREADS 256
#define GXB 40                  // ceil(NN/256)
#define GYB (BB / 2)            // each CTA handles b and b+16
#define NCTA (GXB * GYB)        // 640
#define UB 6                    // explicit batch depth per stream
#define NANCAP 4096

// ---- device scratch (zero-initialized at load; finalizer re-zeros) ----
__device__ float    g_rsum[BB * RR];
__device__ float    g_rcnt[BB * RR];
__device__ unsigned g_done = 0;
__device__ int      g_nan_n = 0;
__device__ int      g_nan_list[NANCAP];

// ---------------------------------------------------------------------------
// Single fused kernel. grid = (40, 16), block = 256.
// Each thread: node n, two independent batch streams b0 = by, b1 = by+16.
// 12 scalar loads in flight per thread at high occupancy.
// ---------------------------------------------------------------------------
__global__ void __launch_bounds__(THREADS)
k_main(const float* __restrict__ seq, const int* __restrict__ cid32,
       float* __restrict__ out) {
    const int tid = threadIdx.x;
    const int b0  = blockIdx.y;
    const int b1  = blockIdx.y + GYB;
    const int n   = blockIdx.x * THREADS + tid;

    __shared__ float srs0[RR], src0[RR], srs1[RR], src1[RR];
    __shared__ int   s_is64;
    if (tid < RR) { srs0[tid] = 0.f; src0[tid] = 0.f; srs1[tid] = 0.f; src1[tid] = 0.f; }
    if (tid < 32) {
        // int64-LE cluster_id => odd int32 words (upper halves) all zero
        unsigned m = __ballot_sync(0xffffffffu, cid32[2 * tid + 1] == 0);
        if (tid == 0) s_is64 = (__popc(m) > 16);
    }
    __syncthreads();

    // ============ Phase 1: dual-stream scalar nanmean ======================
    if (n < NN) {
        const float* p0 = seq + ((size_t)b0 * TT * NN + (size_t)n) * FF;
        const float* p1 = seq + ((size_t)b1 * TT * NN + (size_t)n) * FF;
        float sA0 = 0.f, cA0 = 0.f, sB0 = 0.f, cB0 = 0.f;
        float sA1 = 0.f, cA1 = 0.f, sB1 = 0.f, cB1 = 0.f;
#pragma unroll
        for (int tb = 0; tb < TT / UB; tb++) {
            float v0[UB], v1[UB];                    // 12 independent LDGs
#pragma unroll
            for (int u = 0; u < UB; u++) {
                v0[u] = __ldcs(p0 + (size_t)(tb * UB + u) * NN * FF);
                v1[u] = __ldcs(p1 + (size_t)(tb * UB + u) * NN * FF);
            }
#pragma unroll
            for (int u = 0; u < UB; u += 2) {
                if (v0[u]   == v0[u])   { sA0 += v0[u];   cA0 += 1.f; }
                if (v0[u+1] == v0[u+1]) { sB0 += v0[u+1]; cB0 += 1.f; }
                if (v1[u]   == v1[u])   { sA1 += v1[u];   cA1 += 1.f; }
                if (v1[u+1] == v1[u+1]) { sB1 += v1[u+1]; cB1 += 1.f; }
            }
        }
        const float c0  = cA0 + cB0;
        const float c1  = cA1 + cB1;
        const float tm0 = (sA0 + sB0) / c0;          // 0/0 -> NaN
        const float tm1 = (sA1 + sB1) / c1;

        float* op0 = out + (size_t)b0 * HH * NN + n;
        float* op1 = out + (size_t)b1 * HH * NN + n;
#pragma unroll
        for (int h = 0; h < HH; h++) {
            __stcs(op0 + (size_t)h * NN, tm0);
            __stcs(op1 + (size_t)h * NN, tm1);
        }

        const int rg = s_is64 ? cid32[2 * n] : cid32[n];
        if (c0 > 0.f) { atomicAdd(&srs0[rg], tm0); atomicAdd(&src0[rg], 1.f); }
        else { int s = atomicAdd(&g_nan_n, 1); if (s < NANCAP) g_nan_list[s] = b0 * NN + n; }
        if (c1 > 0.f) { atomicAdd(&srs1[rg], tm1); atomicAdd(&src1[rg], 1.f); }
        else { int s = atomicAdd(&g_nan_n, 1); if (s < NANCAP) g_nan_list[s] = b1 * NN + n; }
    }
    __syncthreads();
    if (tid < RR) {
        if (src0[tid] != 0.f) {
            atomicAdd(&g_rsum[b0 * RR + tid], srs0[tid]);
            atomicAdd(&g_rcnt[b0 * RR + tid], src0[tid]);
        }
        if (src1[tid] != 0.f) {
            atomicAdd(&g_rsum[b1 * RR + tid], srs1[tid]);
            atomicAdd(&g_rcnt[b1 * RR + tid], src1[tid]);
        }
    }

    // ================= completion: last block finalizes ====================
    __shared__ bool s_last;
    __syncthreads();
    if (tid == 0) {
        __threadfence();
        s_last = (atomicAdd(&g_done, 1u) == NCTA - 1);
    }
    __syncthreads();
    if (!s_last) return;

    __threadfence();                                 // acquire others' writes

    __shared__ float s_gs, s_gc, s_2s, s_2c;
    if (tid == 0) { s_gs = 0.f; s_gc = 0.f; s_2s = 0.f; s_2c = 0.f; }
    __syncthreads();

    float rs[3], rc[3];                              // 640 pairs / 256 thr
#pragma unroll
    for (int q = 0; q < 3; q++) {
        int pidx = tid + q * THREADS;
        if (pidx < BB * RR) {
            rs[q] = g_rsum[pidx]; rc[q] = g_rcnt[pidx];
            atomicAdd(&s_gs, rs[q]);
            atomicAdd(&s_gc, rc[q]);
            if (rc[q] > 0.f) { atomicAdd(&s_2s, rs[q] / rc[q]); atomicAdd(&s_2c, 1.f); }
        }
    }
    __syncthreads();
    const float g1 = s_gs / s_gc;                    // nanmean(pred)
    const float g2 = s_2s / s_2c;                    // nanmean(regional)

    float* oreg = out + (size_t)BB * HH * NN;
#pragma unroll
    for (int q = 0; q < 3; q++) {
        int pidx = tid + q * THREADS;
        if (pidx < BB * RR) {
            float val = (rc[q] > 0.f) ? rs[q] / rc[q] : g2;
            int pb = pidx / RR, pr = pidx % RR;
#pragma unroll
            for (int h = 0; h < HH; h++)
                oreg[(pb * HH + h) * RR + pr] = val;
        }
    }

    // NaN backfill of out_pred (expected zero entries)
    int nn = min(g_nan_n, NANCAP);
    for (int i = tid; i < nn; i += THREADS) {
        int idx = g_nan_list[i];
        int nb = idx / NN, nd = idx % NN;
#pragma unroll
        for (int h = 0; h < HH; h++)
            out[((size_t)nb * HH + h) * NN + nd] = g1;
    }

    // reset scratch for next graph replay
    __syncthreads();
    for (int pidx = tid; pidx < BB * RR; pidx += THREADS) {
        g_rsum[pidx] = 0.f; g_rcnt[pidx] = 0.f;
    }
    if (tid == 0) { g_done = 0; g_nan_n = 0; }
}

// ---------------------------------------------------------------------------
extern "C" void kernel_launch(void* const* d_in, const int* in_sizes, int n_in,
                              void* d_out, int out_size) {
    const float* seq   = (const float*)d_in[0];
    const int*   cid32 = (const int*)d_in[1];
    float*       out   = (float*)d_out;

    dim3 grid(GXB, GYB);
    k_main<<<grid, THREADS>>>(seq, cid32, out);
}